// round 12
// baseline (speedup 1.0000x reference)
#include <cuda_runtime.h>

// Problem constants (B=32, S=4096, 22 joints, 20 output joints)
#define FRAMES   (32 * 4096)
#define TPB      128
#define NBLK     (FRAMES / TPB)   // 1024

__device__ float    g_partial[NBLK];
__device__ unsigned g_count = 0;

struct V3 { float x, y, z; };
struct M3 { V3 c0, c1, c2; };   // columns

__device__ __forceinline__ V3 mk3(float x, float y, float z) { V3 v; v.x=x; v.y=y; v.z=z; return v; }
__device__ __forceinline__ V3 v_add(V3 a, V3 b) { return mk3(a.x+b.x, a.y+b.y, a.z+b.z); }

__device__ __forceinline__ V3 matvec(const M3& m, V3 v) {
    return mk3(fmaf(m.c0.x, v.x, fmaf(m.c1.x, v.y, m.c2.x * v.z)),
               fmaf(m.c0.y, v.x, fmaf(m.c1.y, v.y, m.c2.y * v.z)),
               fmaf(m.c0.z, v.x, fmaf(m.c1.z, v.y, m.c2.z * v.z)));
}
__device__ __forceinline__ M3 matmul(const M3& a, const M3& b) {
    M3 r; r.c0 = matvec(a, b.c0); r.c1 = matvec(a, b.c1); r.c2 = matvec(a, b.c2); return r;
}

// 6D continuous rotation rep -> 3x3 matrix (columns b1,b2,b3).
__device__ __forceinline__ M3 conv6d(V3 a1, V3 a2) {
    float n1 = fmaf(a1.x, a1.x, fmaf(a1.y, a1.y, a1.z * a1.z));
    float i1 = rsqrtf(fmaxf(n1, 1e-24f));
    V3 b1 = mk3(a1.x * i1, a1.y * i1, a1.z * i1);

    float dp = fmaf(b1.x, a2.x, fmaf(b1.y, a2.y, b1.z * a2.z));
    V3 t = mk3(fmaf(-dp, b1.x, a2.x), fmaf(-dp, b1.y, a2.y), fmaf(-dp, b1.z, a2.z));
    float n2 = fmaf(t.x, t.x, fmaf(t.y, t.y, t.z * t.z));
    float i2 = rsqrtf(fmaxf(n2, 1e-24f));
    V3 b2 = mk3(t.x * i2, t.y * i2, t.z * i2);

    V3 b3 = mk3(b1.y * b2.z - b1.z * b2.y,
                b1.z * b2.x - b1.x * b2.z,
                b1.x * b2.y - b1.y * b2.x);
    M3 m; m.c0 = b1; m.c1 = b2; m.c2 = b3; return m;
}

// two alignment forms of a 6-float span inside consecutive float4s
__device__ __forceinline__ M3 convA(float4 p, float4 q) {   // span starts at comp 0
    return conv6d(mk3(p.x, p.y, p.z), mk3(p.w, q.x, q.y));
}
__device__ __forceinline__ M3 convB(float4 p, float4 q) {   // span starts at comp 2
    return conv6d(mk3(p.z, p.w, q.x), mk3(q.y, q.z, q.w));
}

__device__ __forceinline__ float dst(V3 p, V3 g) {
    float dx = p.x - g.x, dy = p.y - g.y, dz = p.z - g.z;
    return sqrtf(fmaf(dx, dx, fmaf(dy, dy, dz * dz)));
}

// R4 champion structure, squeezed to 5 CTAs/SM (reduction scratch reuses spred).
__global__ void __launch_bounds__(TPB, 5)
fk_mpjpe_kernel(const float* __restrict__ pred,   // [FRAMES, 20, 3]
                const float* __restrict__ rot,    // [FRAMES, 22, 6]
                const float* __restrict__ off,    // [22, 3]
                float* __restrict__ out)
{
    // rows padded (13 / 9 float4) -> conflict-free LDS.128 per quarter-warp
    __shared__ float4 srot [TPB * 13];   // 12 rot words per frame + pad
    __shared__ float4 spred[TPB * 9];    //  8 pred words per frame + pad
    __shared__ float  soff[66];
    __shared__ float  wsum[TPB / 32];
    __shared__ bool   is_last;

    const int tid = threadIdx.x;
    const size_t f0 = (size_t)blockIdx.x * TPB;
    const float4* Rg = (const float4*)rot  + f0 * 33;
    const float4* Pg = (const float4*)pred + f0 * 15;

    if (tid < 66) soff[tid] = off[tid];

    // ================= PHASE 1 staging: rot words 3..14, pred words 0..7 (coalesced)
    #pragma unroll
    for (int j = 0; j < 12; j++) {
        unsigned i = tid + j * TPB;
        unsigned fr = i / 12u, w = i % 12u;
        srot[fr * 13 + w] = __ldg(Rg + fr * 33 + 3 + w);
    }
    #pragma unroll
    for (int j = 0; j < 8; j++) {
        unsigned i = tid + j * TPB;
        unsigned fr = i >> 3, w = i & 7u;
        spred[fr * 9 + w] = __ldg(Pg + fr * 15 + w);
    }
    __syncthreads();

    const float4* q = srot  + tid * 13 - 3;   // q[w] valid for w = 3..14
    const float4* P = spred + tid * 9;        // P[w] valid for w = 0..7

    #define OFF3(i) mk3(soff[3*(i)], soff[3*(i)+1], soff[3*(i)+2])

    float acc = 0.f;
    M3 G9; V3 pos9;

    // ---- chain: 3 -> 6 -> 9 (trunk; G9/pos9 carried to phase 2) ----
    {
        M3 G3 = convB(q[4], q[5]);
        V3 pos3 = OFF3(3);
        float4 p0 = P[0], p1 = P[1];
        acc += dst(mk3(p0.w, p1.x, p1.y), pos3);                  // k=1
        M3 G6 = matmul(G3, convA(q[9], q[10]));
        V3 pos6 = v_add(pos3, matvec(G3, OFF3(6)));
        float4 p3 = P[3];
        acc += dst(mk3(p3.x, p3.y, p3.z), pos6);                  // k=4
        G9 = matmul(G6, convB(q[13], q[14]));
        pos9 = v_add(pos6, matvec(G6, OFF3(9)));
        float4 p5 = P[5];
        acc += dst(mk3(p5.y, p5.z, p5.w), pos9);                  // k=7
    }

    // ---- chain: 1(identity) -> 4 -> 7 -> 10 ----
    {
        M3 G4 = convA(q[6], q[7]);
        V3 pos4 = v_add(OFF3(1), OFF3(4));
        float4 p1 = P[1], p2 = P[2];
        acc += dst(mk3(p1.z, p1.w, p2.x), pos4);                  // k=2
        M3 G7 = matmul(G4, convB(q[10], q[11]));
        V3 pos7 = v_add(pos4, matvec(G4, OFF3(7)));
        float4 p3 = P[3], p4 = P[4];
        acc += dst(mk3(p3.w, p4.x, p4.y), pos7);                  // k=5
        V3 pos10 = v_add(pos7, matvec(G7, OFF3(10)));
        float4 p6 = P[6];
        acc += dst(mk3(p6.x, p6.y, p6.z), pos10);                 // k=8
    }

    // ---- chain: 2 -> 5 -> 8 -> 11 ----
    {
        M3 G2 = convA(q[3], q[4]);
        V3 pos2 = OFF3(2);
        float4 p0 = P[0];
        acc += dst(mk3(p0.x, p0.y, p0.z), pos2);                  // k=0
        M3 G5 = matmul(G2, convB(q[7], q[8]));
        V3 pos5 = v_add(pos2, matvec(G2, OFF3(5)));
        float4 p2 = P[2];
        acc += dst(mk3(p2.y, p2.z, p2.w), pos5);                  // k=3
        M3 G8 = matmul(G5, convA(q[12], q[13]));
        V3 pos8 = v_add(pos5, matvec(G5, OFF3(8)));
        float4 p4 = P[4], p5 = P[5];
        acc += dst(mk3(p4.z, p4.w, p5.x), pos8);                  // k=6
        V3 pos11 = v_add(pos8, matvec(G8, OFF3(11)));
        float4 p6 = P[6], p7 = P[7];
        acc += dst(mk3(p6.w, p7.x, p7.y), pos11);                 // k=9
    }

    // ================= PHASE 2 staging: rot words 18..29, pred words 7..14
    __syncthreads();   // all phase-1 smem reads done
    #pragma unroll
    for (int j = 0; j < 12; j++) {
        unsigned i = tid + j * TPB;
        unsigned fr = i / 12u, w = i % 12u;
        srot[fr * 13 + w] = __ldg(Rg + fr * 33 + 18 + w);
    }
    #pragma unroll
    for (int j = 0; j < 8; j++) {
        unsigned i = tid + j * TPB;
        unsigned fr = i >> 3, w = i & 7u;
        spred[fr * 9 + w] = __ldg(Pg + fr * 15 + 7 + w);
    }
    __syncthreads();

    const float4* r2 = srot  + tid * 13 - 18;  // r2[w] valid for w = 18..29
    const float4* P2 = spred + tid * 9 - 7;    // P2[w] valid for w = 7..14

    // ---- branch 12 -> 15 ----
    {
        M3 G12 = matmul(G9, convA(r2[18], r2[19]));
        V3 pos12 = v_add(pos9, matvec(G9, OFF3(12)));
        float4 p7 = P2[7], p8 = P2[8];
        acc += dst(mk3(p7.z, p7.w, p8.x), pos12);                 // k=10
        V3 pos15 = v_add(pos12, matvec(G12, OFF3(15)));
        float4 p9 = P2[9], p10 = P2[10];
        acc += dst(mk3(p9.w, p10.x, p10.y), pos15);               // k=13
    }

    // ---- branch 13 -> 16 -> 18 -> 20 ----
    {
        M3 G13 = matmul(G9, convB(r2[19], r2[20]));
        V3 pos13 = v_add(pos9, matvec(G9, OFF3(13)));
        float4 p8 = P2[8];
        acc += dst(mk3(p8.y, p8.z, p8.w), pos13);                 // k=11
        M3 G16 = matmul(G13, convA(r2[24], r2[25]));
        V3 pos16 = v_add(pos13, matvec(G13, OFF3(16)));
        float4 p10 = P2[10], p11 = P2[11];
        acc += dst(mk3(p10.z, p10.w, p11.x), pos16);              // k=14
        M3 G18 = matmul(G16, convA(r2[27], r2[28]));
        V3 pos18 = v_add(pos16, matvec(G16, OFF3(18)));
        float4 p12 = P2[12];
        acc += dst(mk3(p12.x, p12.y, p12.z), pos18);              // k=16
        V3 pos20 = v_add(pos18, matvec(G18, OFF3(20)));
        float4 p13 = P2[13], p14 = P2[14];
        acc += dst(mk3(p13.z, p13.w, p14.x), pos20);              // k=18
    }

    // ---- branch 14 -> 17 -> 19 -> 21 ----
    {
        M3 G14 = matmul(G9, convA(r2[21], r2[22]));
        V3 pos14 = v_add(pos9, matvec(G9, OFF3(14)));
        float4 p9 = P2[9];
        acc += dst(mk3(p9.x, p9.y, p9.z), pos14);                 // k=12
        M3 G17 = matmul(G14, convB(r2[25], r2[26]));
        V3 pos17 = v_add(pos14, matvec(G14, OFF3(17)));
        float4 p11 = P2[11];
        acc += dst(mk3(p11.y, p11.z, p11.w), pos17);              // k=15
        M3 G19 = matmul(G17, convB(r2[28], r2[29]));
        V3 pos19 = v_add(pos17, matvec(G17, OFF3(19)));
        float4 p12 = P2[12], p13 = P2[13];
        acc += dst(mk3(p12.w, p13.x, p13.y), pos19);              // k=17
        V3 pos21 = v_add(pos19, matvec(G19, OFF3(21)));
        float4 p14 = P2[14];
        acc += dst(mk3(p14.y, p14.z, p14.w), pos21);              // k=19
    }

    #undef OFF3

    // ---- deterministic block reduction ----
    #pragma unroll
    for (int o = 16; o > 0; o >>= 1)
        acc += __shfl_down_sync(0xffffffffu, acc, o);

    int lane = tid & 31, wid = tid >> 5;
    if (lane == 0) wsum[wid] = acc;
    __syncthreads();

    if (tid == 0) {
        float s = 0.f;
        #pragma unroll
        for (int i = 0; i < TPB / 32; i++) s += wsum[i];
        g_partial[blockIdx.x] = s;
        __threadfence();
        unsigned prev = atomicAdd(&g_count, 1u);
        is_last = (prev == NBLK - 1);
    }
    __syncthreads();

    // ---- last block folds all partials (fixed order -> deterministic) ----
    // scratch reuses spred (all spred reads completed above) -> no extra smem
    if (is_last) {
        float* sh = (float*)spred;
        float s = 0.f;
        #pragma unroll
        for (int j = 0; j < NBLK / TPB; j++) {
            const float* addr = g_partial + tid + j * TPB;
            float v;
            asm volatile("ld.global.cg.f32 %0, [%1];" : "=f"(v) : "l"(addr));
            s += v;
        }
        sh[tid] = s;
        __syncthreads();
        #pragma unroll
        for (int k = TPB / 2; k > 0; k >>= 1) {
            if (tid < k) sh[tid] += sh[tid + k];
            __syncthreads();
        }
        if (tid == 0) {
            out[0] = sh[0] * (1000.0f / (float)(FRAMES * 20));
            g_count = 0;   // reset for next graph replay
        }
    }
}

extern "C" void kernel_launch(void* const* d_in, const int* in_sizes, int n_in,
                              void* d_out, int out_size) {
    const float* pred = (const float*)d_in[0];   // pred_pos [32,4096,20,3]
    const float* rot  = (const float*)d_in[1];   // gt_rot   [32,4096,22,6]
    const float* off  = (const float*)d_in[2];   // offsets  [22,3]
    float* out = (float*)d_out;

    fk_mpjpe_kernel<<<NBLK, TPB>>>(pred, rot, off, out);
}

// round 13
// speedup vs baseline: 1.4064x; 1.4064x over previous
#include <cuda_runtime.h>

// Problem constants (B=32, S=4096, 22 joints, 20 output joints)
#define FRAMES   (32 * 4096)
#define TPB      128
#define NBLK     (FRAMES / TPB)   // 1024

__device__ float    g_partial[NBLK];
__device__ unsigned g_count = 0;

struct V3 { float x, y, z; };
struct M3 { V3 c0, c1, c2; };   // columns

__device__ __forceinline__ V3 mk3(float x, float y, float z) { V3 v; v.x=x; v.y=y; v.z=z; return v; }
__device__ __forceinline__ V3 v_add(V3 a, V3 b) { return mk3(a.x+b.x, a.y+b.y, a.z+b.z); }

__device__ __forceinline__ V3 matvec(const M3& m, V3 v) {
    return mk3(fmaf(m.c0.x, v.x, fmaf(m.c1.x, v.y, m.c2.x * v.z)),
               fmaf(m.c0.y, v.x, fmaf(m.c1.y, v.y, m.c2.y * v.z)),
               fmaf(m.c0.z, v.x, fmaf(m.c1.z, v.y, m.c2.z * v.z)));
}
__device__ __forceinline__ M3 matmul(const M3& a, const M3& b) {
    M3 r; r.c0 = matvec(a, b.c0); r.c1 = matvec(a, b.c1); r.c2 = matvec(a, b.c2); return r;
}

// 6D continuous rotation rep -> 3x3 matrix (columns b1,b2,b3).
__device__ __forceinline__ M3 conv6d(V3 a1, V3 a2) {
    float n1 = fmaf(a1.x, a1.x, fmaf(a1.y, a1.y, a1.z * a1.z));
    float i1 = rsqrtf(fmaxf(n1, 1e-24f));
    V3 b1 = mk3(a1.x * i1, a1.y * i1, a1.z * i1);

    float dp = fmaf(b1.x, a2.x, fmaf(b1.y, a2.y, b1.z * a2.z));
    V3 t = mk3(fmaf(-dp, b1.x, a2.x), fmaf(-dp, b1.y, a2.y), fmaf(-dp, b1.z, a2.z));
    float n2 = fmaf(t.x, t.x, fmaf(t.y, t.y, t.z * t.z));
    float i2 = rsqrtf(fmaxf(n2, 1e-24f));
    V3 b2 = mk3(t.x * i2, t.y * i2, t.z * i2);

    V3 b3 = mk3(b1.y * b2.z - b1.z * b2.y,
                b1.z * b2.x - b1.x * b2.z,
                b1.x * b2.y - b1.y * b2.x);
    M3 m; m.c0 = b1; m.c1 = b2; m.c2 = b3; return m;
}

// two alignment forms of a 6-float span inside consecutive float4s
__device__ __forceinline__ M3 convA(float4 p, float4 q) {   // span starts at comp 0
    return conv6d(mk3(p.x, p.y, p.z), mk3(p.w, q.x, q.y));
}
__device__ __forceinline__ M3 convB(float4 p, float4 q) {   // span starts at comp 2
    return conv6d(mk3(p.z, p.w, q.x), mk3(q.y, q.z, q.w));
}

__device__ __forceinline__ float dst(V3 p, V3 g) {
    float dx = p.x - g.x, dy = p.y - g.y, dz = p.z - g.z;
    return sqrtf(fmaf(dx, dx, fmaf(dy, dy, dz * dz)));
}

// Exact R4 champion structure; regs free (no minBlocks cap -> no spills).
__global__ void __launch_bounds__(TPB)
fk_mpjpe_kernel(const float* __restrict__ pred,   // [FRAMES, 20, 3]
                const float* __restrict__ rot,    // [FRAMES, 22, 6]
                const float* __restrict__ off,    // [22, 3]
                float* __restrict__ out)
{
    // rows padded (13 / 9 float4) -> conflict-free LDS.128 per quarter-warp
    __shared__ float4 srot [TPB * 13];   // 12 rot words per frame + pad
    __shared__ float4 spred[TPB * 9];    //  8 pred words per frame + pad
    __shared__ float  soff[66];
    __shared__ float  wsum[TPB / 32];
    __shared__ bool   is_last;

    const int tid = threadIdx.x;
    const size_t f0 = (size_t)blockIdx.x * TPB;
    const float4* Rg = (const float4*)rot  + f0 * 33;
    const float4* Pg = (const float4*)pred + f0 * 15;

    if (tid < 66) soff[tid] = off[tid];

    // ================= PHASE 1 staging: rot words 3..14, pred words 0..7 (coalesced)
    #pragma unroll
    for (int j = 0; j < 12; j++) {
        unsigned i = tid + j * TPB;
        unsigned fr = i / 12u, w = i % 12u;
        srot[fr * 13 + w] = __ldg(Rg + fr * 33 + 3 + w);
    }
    #pragma unroll
    for (int j = 0; j < 8; j++) {
        unsigned i = tid + j * TPB;
        unsigned fr = i >> 3, w = i & 7u;
        spred[fr * 9 + w] = __ldg(Pg + fr * 15 + w);
    }
    __syncthreads();

    const float4* q = srot  + tid * 13 - 3;   // q[w] valid for w = 3..14
    const float4* P = spred + tid * 9;        // P[w] valid for w = 0..7

    #define OFF3(i) mk3(soff[3*(i)], soff[3*(i)+1], soff[3*(i)+2])

    float acc = 0.f;
    M3 G9; V3 pos9;

    // ---- chain: 3 -> 6 -> 9 (trunk; G9/pos9 carried to phase 2) ----
    {
        M3 G3 = convB(q[4], q[5]);
        V3 pos3 = OFF3(3);
        float4 p0 = P[0], p1 = P[1];
        acc += dst(mk3(p0.w, p1.x, p1.y), pos3);                  // k=1
        M3 G6 = matmul(G3, convA(q[9], q[10]));
        V3 pos6 = v_add(pos3, matvec(G3, OFF3(6)));
        float4 p3 = P[3];
        acc += dst(mk3(p3.x, p3.y, p3.z), pos6);                  // k=4
        G9 = matmul(G6, convB(q[13], q[14]));
        pos9 = v_add(pos6, matvec(G6, OFF3(9)));
        float4 p5 = P[5];
        acc += dst(mk3(p5.y, p5.z, p5.w), pos9);                  // k=7
    }

    // ---- chain: 1(identity) -> 4 -> 7 -> 10 ----
    {
        M3 G4 = convA(q[6], q[7]);
        V3 pos4 = v_add(OFF3(1), OFF3(4));
        float4 p1 = P[1], p2 = P[2];
        acc += dst(mk3(p1.z, p1.w, p2.x), pos4);                  // k=2
        M3 G7 = matmul(G4, convB(q[10], q[11]));
        V3 pos7 = v_add(pos4, matvec(G4, OFF3(7)));
        float4 p3 = P[3], p4 = P[4];
        acc += dst(mk3(p3.w, p4.x, p4.y), pos7);                  // k=5
        V3 pos10 = v_add(pos7, matvec(G7, OFF3(10)));
        float4 p6 = P[6];
        acc += dst(mk3(p6.x, p6.y, p6.z), pos10);                 // k=8
    }

    // ---- chain: 2 -> 5 -> 8 -> 11 ----
    {
        M3 G2 = convA(q[3], q[4]);
        V3 pos2 = OFF3(2);
        float4 p0 = P[0];
        acc += dst(mk3(p0.x, p0.y, p0.z), pos2);                  // k=0
        M3 G5 = matmul(G2, convB(q[7], q[8]));
        V3 pos5 = v_add(pos2, matvec(G2, OFF3(5)));
        float4 p2 = P[2];
        acc += dst(mk3(p2.y, p2.z, p2.w), pos5);                  // k=3
        M3 G8 = matmul(G5, convA(q[12], q[13]));
        V3 pos8 = v_add(pos5, matvec(G5, OFF3(8)));
        float4 p4 = P[4], p5 = P[5];
        acc += dst(mk3(p4.z, p4.w, p5.x), pos8);                  // k=6
        V3 pos11 = v_add(pos8, matvec(G8, OFF3(11)));
        float4 p6 = P[6], p7 = P[7];
        acc += dst(mk3(p6.w, p7.x, p7.y), pos11);                 // k=9
    }

    // ================= PHASE 2 staging: rot words {18..22, 24..29} (word 23 is never
    // read -> 11 words, 2MB less traffic), pred words 7..14
    __syncthreads();   // all phase-1 smem reads done
    #pragma unroll
    for (int j = 0; j < 11; j++) {
        unsigned i = tid + j * TPB;
        unsigned fr = i / 11u, ws = i % 11u;
        unsigned w = (ws < 5u) ? (18u + ws) : (19u + ws);   // skip word 23
        srot[fr * 13 + (w - 18u)] = __ldg(Rg + fr * 33 + w);
    }
    #pragma unroll
    for (int j = 0; j < 8; j++) {
        unsigned i = tid + j * TPB;
        unsigned fr = i >> 3, w = i & 7u;
        spred[fr * 9 + w] = __ldg(Pg + fr * 15 + 7 + w);
    }
    __syncthreads();

    const float4* r2 = srot  + tid * 13 - 18;  // r2[w] valid for w = 18..29 (23 unused)
    const float4* P2 = spred + tid * 9 - 7;    // P2[w] valid for w = 7..14

    // ---- branch 12 -> 15 ----
    {
        M3 G12 = matmul(G9, convA(r2[18], r2[19]));
        V3 pos12 = v_add(pos9, matvec(G9, OFF3(12)));
        float4 p7 = P2[7], p8 = P2[8];
        acc += dst(mk3(p7.z, p7.w, p8.x), pos12);                 // k=10
        V3 pos15 = v_add(pos12, matvec(G12, OFF3(15)));
        float4 p9 = P2[9], p10 = P2[10];
        acc += dst(mk3(p9.w, p10.x, p10.y), pos15);               // k=13
    }

    // ---- branch 13 -> 16 -> 18 -> 20 ----
    {
        M3 G13 = matmul(G9, convB(r2[19], r2[20]));
        V3 pos13 = v_add(pos9, matvec(G9, OFF3(13)));
        float4 p8 = P2[8];
        acc += dst(mk3(p8.y, p8.z, p8.w), pos13);                 // k=11
        M3 G16 = matmul(G13, convA(r2[24], r2[25]));
        V3 pos16 = v_add(pos13, matvec(G13, OFF3(16)));
        float4 p10 = P2[10], p11 = P2[11];
        acc += dst(mk3(p10.z, p10.w, p11.x), pos16);              // k=14
        M3 G18 = matmul(G16, convA(r2[27], r2[28]));
        V3 pos18 = v_add(pos16, matvec(G16, OFF3(18)));
        float4 p12 = P2[12];
        acc += dst(mk3(p12.x, p12.y, p12.z), pos18);              // k=16
        V3 pos20 = v_add(pos18, matvec(G18, OFF3(20)));
        float4 p13 = P2[13], p14 = P2[14];
        acc += dst(mk3(p13.z, p13.w, p14.x), pos20);              // k=18
    }

    // ---- branch 14 -> 17 -> 19 -> 21 ----
    {
        M3 G14 = matmul(G9, convA(r2[21], r2[22]));
        V3 pos14 = v_add(pos9, matvec(G9, OFF3(14)));
        float4 p9 = P2[9];
        acc += dst(mk3(p9.x, p9.y, p9.z), pos14);                 // k=12
        M3 G17 = matmul(G14, convB(r2[25], r2[26]));
        V3 pos17 = v_add(pos14, matvec(G14, OFF3(17)));
        float4 p11 = P2[11];
        acc += dst(mk3(p11.y, p11.z, p11.w), pos17);              // k=15
        M3 G19 = matmul(G17, convB(r2[28], r2[29]));
        V3 pos19 = v_add(pos17, matvec(G17, OFF3(19)));
        float4 p12 = P2[12], p13 = P2[13];
        acc += dst(mk3(p12.w, p13.x, p13.y), pos19);              // k=17
        V3 pos21 = v_add(pos19, matvec(G19, OFF3(21)));
        float4 p14 = P2[14];
        acc += dst(mk3(p14.y, p14.z, p14.w), pos21);              // k=19
    }

    #undef OFF3

    // ---- deterministic block reduction ----
    #pragma unroll
    for (int o = 16; o > 0; o >>= 1)
        acc += __shfl_down_sync(0xffffffffu, acc, o);

    int lane = tid & 31, wid = tid >> 5;
    if (lane == 0) wsum[wid] = acc;
    __syncthreads();

    if (tid == 0) {
        float s = 0.f;
        #pragma unroll
        for (int i = 0; i < TPB / 32; i++) s += wsum[i];
        g_partial[blockIdx.x] = s;
        __threadfence();
        unsigned prev = atomicAdd(&g_count, 1u);
        is_last = (prev == NBLK - 1);
    }
    __syncthreads();

    // ---- last block folds all partials (fixed order -> deterministic) ----
    if (is_last) {
        float s = 0.f;
        #pragma unroll
        for (int j = 0; j < NBLK / TPB; j++) {
            const float* addr = g_partial + tid + j * TPB;
            float v;
            asm volatile("ld.global.cg.f32 %0, [%1];" : "=f"(v) : "l"(addr));
            s += v;
        }
        __shared__ float sh[TPB];
        sh[tid] = s;
        __syncthreads();
        #pragma unroll
        for (int k = TPB / 2; k > 0; k >>= 1) {
            if (tid < k) sh[tid] += sh[tid + k];
            __syncthreads();
        }
        if (tid == 0) {
            out[0] = sh[0] * (1000.0f / (float)(FRAMES * 20));
            g_count = 0;   // reset for next graph replay
        }
    }
}

extern "C" void kernel_launch(void* const* d_in, const int* in_sizes, int n_in,
                              void* d_out, int out_size) {
    const float* pred = (const float*)d_in[0];   // pred_pos [32,4096,20,3]
    const float* rot  = (const float*)d_in[1];   // gt_rot   [32,4096,22,6]
    const float* off  = (const float*)d_in[2];   // offsets  [22,3]
    float* out = (float*)d_out;

    fk_mpjpe_kernel<<<NBLK, TPB>>>(pred, rot, off, out);
}

// round 14
// speedup vs baseline: 1.5144x; 1.0768x over previous
#include <cuda_runtime.h>

// Problem constants (B=32, S=4096, 22 joints, 20 output joints)
#define FRAMES   (32 * 4096)
#define TPB      128
#define NBLK     (FRAMES / TPB)   // 1024

__device__ float    g_partial[NBLK];
__device__ unsigned g_count = 0;

struct V3 { float x, y, z; };
struct M3 { V3 c0, c1, c2; };   // columns

__device__ __forceinline__ V3 mk3(float x, float y, float z) { V3 v; v.x=x; v.y=y; v.z=z; return v; }
__device__ __forceinline__ V3 v_add(V3 a, V3 b) { return mk3(a.x+b.x, a.y+b.y, a.z+b.z); }

__device__ __forceinline__ V3 matvec(const M3& m, V3 v) {
    return mk3(fmaf(m.c0.x, v.x, fmaf(m.c1.x, v.y, m.c2.x * v.z)),
               fmaf(m.c0.y, v.x, fmaf(m.c1.y, v.y, m.c2.y * v.z)),
               fmaf(m.c0.z, v.x, fmaf(m.c1.z, v.y, m.c2.z * v.z)));
}
__device__ __forceinline__ M3 matmul(const M3& a, const M3& b) {
    M3 r; r.c0 = matvec(a, b.c0); r.c1 = matvec(a, b.c1); r.c2 = matvec(a, b.c2); return r;
}

// 6D continuous rotation rep -> 3x3 matrix (columns b1,b2,b3).
__device__ __forceinline__ M3 conv6d(V3 a1, V3 a2) {
    float n1 = fmaf(a1.x, a1.x, fmaf(a1.y, a1.y, a1.z * a1.z));
    float i1 = rsqrtf(fmaxf(n1, 1e-24f));
    V3 b1 = mk3(a1.x * i1, a1.y * i1, a1.z * i1);

    float dp = fmaf(b1.x, a2.x, fmaf(b1.y, a2.y, b1.z * a2.z));
    V3 t = mk3(fmaf(-dp, b1.x, a2.x), fmaf(-dp, b1.y, a2.y), fmaf(-dp, b1.z, a2.z));
    float n2 = fmaf(t.x, t.x, fmaf(t.y, t.y, t.z * t.z));
    float i2 = rsqrtf(fmaxf(n2, 1e-24f));
    V3 b2 = mk3(t.x * i2, t.y * i2, t.z * i2);

    V3 b3 = mk3(b1.y * b2.z - b1.z * b2.y,
                b1.z * b2.x - b1.x * b2.z,
                b1.x * b2.y - b1.y * b2.x);
    M3 m; m.c0 = b1; m.c1 = b2; m.c2 = b3; return m;
}

// two alignment forms of a 6-float span inside consecutive float4s
__device__ __forceinline__ M3 convA(float4 p, float4 q) {   // span starts at comp 0
    return conv6d(mk3(p.x, p.y, p.z), mk3(p.w, q.x, q.y));
}
__device__ __forceinline__ M3 convB(float4 p, float4 q) {   // span starts at comp 2
    return conv6d(mk3(p.z, p.w, q.x), mk3(q.y, q.z, q.w));
}

__device__ __forceinline__ float dst(V3 p, V3 g) {
    float dx = p.x - g.x, dy = p.y - g.y, dz = p.z - g.z;
    return sqrtf(fmaf(dx, dx, fmaf(dy, dy, dz * dz)));
}

__global__ void __launch_bounds__(TPB)
fk_mpjpe_kernel(const float* __restrict__ pred,   // [FRAMES, 20, 3]
                const float* __restrict__ rot,    // [FRAMES, 22, 6]
                const float* __restrict__ off,    // [22, 3]
                float* __restrict__ out)
{
    // rows padded (13 / 9 float4) -> conflict-free LDS.128 per quarter-warp
    __shared__ float4 srot [TPB * 13];   // 12 rot words per frame + pad
    __shared__ float4 spred[TPB * 9];    //  8 pred words per frame + pad
    __shared__ float  soff[66];
    __shared__ float  wsum[TPB / 32];
    __shared__ bool   is_last;

    const int tid = threadIdx.x;
    const size_t f0 = (size_t)blockIdx.x * TPB;
    const float4* Rg = (const float4*)rot  + f0 * 33;
    const float4* Pg = (const float4*)pred + f0 * 15;

    if (tid < 66) soff[tid] = off[tid];

    // ================= PHASE 1 staging: rot words 3..14, pred words 0..7 (coalesced)
    #pragma unroll
    for (int j = 0; j < 12; j++) {
        unsigned i = tid + j * TPB;
        unsigned fr = i / 12u, w = i % 12u;
        srot[fr * 13 + w] = __ldg(Rg + fr * 33 + 3 + w);
    }
    #pragma unroll
    for (int j = 0; j < 8; j++) {
        unsigned i = tid + j * TPB;
        unsigned fr = i >> 3, w = i & 7u;
        spred[fr * 9 + w] = __ldg(Pg + fr * 15 + w);
    }
    __syncthreads();

    const float4* q = srot  + tid * 13 - 3;   // q[w] valid for w = 3..14
    const float4* P = spred + tid * 9;        // P[w] valid for w = 0..7

    #define OFF3(i) mk3(soff[3*(i)], soff[3*(i)+1], soff[3*(i)+2])

    float acc = 0.f;
    M3 G9; V3 pos9;

    // ---- chain: 3 -> 6 -> 9 (trunk; G9/pos9 carried to phase 2) ----
    {
        M3 G3 = convB(q[4], q[5]);
        V3 pos3 = OFF3(3);
        float4 p0 = P[0], p1 = P[1];
        acc += dst(mk3(p0.w, p1.x, p1.y), pos3);                  // k=1
        M3 G6 = matmul(G3, convA(q[9], q[10]));
        V3 pos6 = v_add(pos3, matvec(G3, OFF3(6)));
        float4 p3 = P[3];
        acc += dst(mk3(p3.x, p3.y, p3.z), pos6);                  // k=4
        G9 = matmul(G6, convB(q[13], q[14]));
        pos9 = v_add(pos6, matvec(G6, OFF3(9)));
        float4 p5 = P[5];
        acc += dst(mk3(p5.y, p5.z, p5.w), pos9);                  // k=7
    }

    // ---- chain: 1(identity) -> 4 -> 7 -> 10 ----
    {
        M3 G4 = convA(q[6], q[7]);
        V3 pos4 = v_add(OFF3(1), OFF3(4));
        float4 p1 = P[1], p2 = P[2];
        acc += dst(mk3(p1.z, p1.w, p2.x), pos4);                  // k=2
        M3 G7 = matmul(G4, convB(q[10], q[11]));
        V3 pos7 = v_add(pos4, matvec(G4, OFF3(7)));
        float4 p3 = P[3], p4 = P[4];
        acc += dst(mk3(p3.w, p4.x, p4.y), pos7);                  // k=5
        V3 pos10 = v_add(pos7, matvec(G7, OFF3(10)));
        float4 p6 = P[6];
        acc += dst(mk3(p6.x, p6.y, p6.z), pos10);                 // k=8
    }

    // ---- chain: 2 -> 5 -> 8 -> 11 ----
    {
        M3 G2 = convA(q[3], q[4]);
        V3 pos2 = OFF3(2);
        float4 p0 = P[0];
        acc += dst(mk3(p0.x, p0.y, p0.z), pos2);                  // k=0
        M3 G5 = matmul(G2, convB(q[7], q[8]));
        V3 pos5 = v_add(pos2, matvec(G2, OFF3(5)));
        float4 p2 = P[2];
        acc += dst(mk3(p2.y, p2.z, p2.w), pos5);                  // k=3
        M3 G8 = matmul(G5, convA(q[12], q[13]));
        V3 pos8 = v_add(pos5, matvec(G5, OFF3(8)));
        float4 p4 = P[4], p5 = P[5];
        acc += dst(mk3(p4.z, p4.w, p5.x), pos8);                  // k=6
        V3 pos11 = v_add(pos8, matvec(G8, OFF3(11)));
        float4 p6 = P[6], p7 = P[7];
        acc += dst(mk3(p6.w, p7.x, p7.y), pos11);                 // k=9
    }

    // ================= PHASE 2 staging: rot words 18..29, pred words 7..14
    __syncthreads();   // all phase-1 smem reads done
    #pragma unroll
    for (int j = 0; j < 12; j++) {
        unsigned i = tid + j * TPB;
        unsigned fr = i / 12u, w = i % 12u;
        srot[fr * 13 + w] = __ldg(Rg + fr * 33 + 18 + w);
    }
    #pragma unroll
    for (int j = 0; j < 8; j++) {
        unsigned i = tid + j * TPB;
        unsigned fr = i >> 3, w = i & 7u;
        spred[fr * 9 + w] = __ldg(Pg + fr * 15 + 7 + w);
    }
    __syncthreads();

    const float4* r2 = srot  + tid * 13 - 18;  // r2[w] valid for w = 18..29
    const float4* P2 = spred + tid * 9 - 7;    // P2[w] valid for w = 7..14

    // ---- branch 12 -> 15 ----
    {
        M3 G12 = matmul(G9, convA(r2[18], r2[19]));
        V3 pos12 = v_add(pos9, matvec(G9, OFF3(12)));
        float4 p7 = P2[7], p8 = P2[8];
        acc += dst(mk3(p7.z, p7.w, p8.x), pos12);                 // k=10
        V3 pos15 = v_add(pos12, matvec(G12, OFF3(15)));
        float4 p9 = P2[9], p10 = P2[10];
        acc += dst(mk3(p9.w, p10.x, p10.y), pos15);               // k=13
    }

    // ---- branch 13 -> 16 -> 18 -> 20 ----
    {
        M3 G13 = matmul(G9, convB(r2[19], r2[20]));
        V3 pos13 = v_add(pos9, matvec(G9, OFF3(13)));
        float4 p8 = P2[8];
        acc += dst(mk3(p8.y, p8.z, p8.w), pos13);                 // k=11
        M3 G16 = matmul(G13, convA(r2[24], r2[25]));
        V3 pos16 = v_add(pos13, matvec(G13, OFF3(16)));
        float4 p10 = P2[10], p11 = P2[11];
        acc += dst(mk3(p10.z, p10.w, p11.x), pos16);              // k=14
        M3 G18 = matmul(G16, convA(r2[27], r2[28]));
        V3 pos18 = v_add(pos16, matvec(G16, OFF3(18)));
        float4 p12 = P2[12];
        acc += dst(mk3(p12.x, p12.y, p12.z), pos18);              // k=16
        V3 pos20 = v_add(pos18, matvec(G18, OFF3(20)));
        float4 p13 = P2[13], p14 = P2[14];
        acc += dst(mk3(p13.z, p13.w, p14.x), pos20);              // k=18
    }

    // ---- branch 14 -> 17 -> 19 -> 21 ----
    {
        M3 G14 = matmul(G9, convA(r2[21], r2[22]));
        V3 pos14 = v_add(pos9, matvec(G9, OFF3(14)));
        float4 p9 = P2[9];
        acc += dst(mk3(p9.x, p9.y, p9.z), pos14);                 // k=12
        M3 G17 = matmul(G14, convB(r2[25], r2[26]));
        V3 pos17 = v_add(pos14, matvec(G14, OFF3(17)));
        float4 p11 = P2[11];
        acc += dst(mk3(p11.y, p11.z, p11.w), pos17);              // k=15
        M3 G19 = matmul(G17, convB(r2[28], r2[29]));
        V3 pos19 = v_add(pos17, matvec(G17, OFF3(19)));
        float4 p12 = P2[12], p13 = P2[13];
        acc += dst(mk3(p12.w, p13.x, p13.y), pos19);              // k=17
        V3 pos21 = v_add(pos19, matvec(G19, OFF3(21)));
        float4 p14 = P2[14];
        acc += dst(mk3(p14.y, p14.z, p14.w), pos21);              // k=19
    }

    #undef OFF3

    // ---- deterministic block reduction ----
    #pragma unroll
    for (int o = 16; o > 0; o >>= 1)
        acc += __shfl_down_sync(0xffffffffu, acc, o);

    int lane = tid & 31, wid = tid >> 5;
    if (lane == 0) wsum[wid] = acc;
    __syncthreads();

    if (tid == 0) {
        float s = 0.f;
        #pragma unroll
        for (int i = 0; i < TPB / 32; i++) s += wsum[i];
        g_partial[blockIdx.x] = s;
        __threadfence();
        unsigned prev = atomicAdd(&g_count, 1u);
        is_last = (prev == NBLK - 1);
    }
    __syncthreads();

    // ---- last block folds all partials (fixed order -> deterministic) ----
    if (is_last) {
        float s = 0.f;
        #pragma unroll
        for (int j = 0; j < NBLK / TPB; j++) {
            const float* addr = g_partial + tid + j * TPB;
            float v;
            asm volatile("ld.global.cg.f32 %0, [%1];" : "=f"(v) : "l"(addr));
            s += v;
        }
        __shared__ float sh[TPB];
        sh[tid] = s;
        __syncthreads();
        #pragma unroll
        for (int k = TPB / 2; k > 0; k >>= 1) {
            if (tid < k) sh[tid] += sh[tid + k];
            __syncthreads();
        }
        if (tid == 0) {
            out[0] = sh[0] * (1000.0f / (float)(FRAMES * 20));
            g_count = 0;   // reset for next graph replay
        }
    }
}

extern "C" void kernel_launch(void* const* d_in, const int* in_sizes, int n_in,
                              void* d_out, int out_size) {
    const float* pred = (const float*)d_in[0];   // pred_pos [32,4096,20,3]
    const float* rot  = (const float*)d_in[1];   // gt_rot   [32,4096,22,6]
    const float* off  = (const float*)d_in[2];   // offsets  [22,3]
    float* out = (float*)d_out;

    fk_mpjpe_kernel<<<NBLK, TPB>>>(pred, rot, off, out);
}

// round 15
// speedup vs baseline: 1.5333x; 1.0125x over previous
#include <cuda_runtime.h>
#include <cstdint>

// Problem constants (B=32, S=4096, 22 joints, 20 output joints)
#define FRAMES   (32 * 4096)
#define TPB      128
#define NBLK     (FRAMES / TPB)   // 1024

__device__ float    g_partial[NBLK];
__device__ unsigned g_count = 0;

struct V3 { float x, y, z; };
struct M3 { V3 c0, c1, c2; };   // columns

__device__ __forceinline__ V3 mk3(float x, float y, float z) { V3 v; v.x=x; v.y=y; v.z=z; return v; }
__device__ __forceinline__ V3 v_add(V3 a, V3 b) { return mk3(a.x+b.x, a.y+b.y, a.z+b.z); }

__device__ __forceinline__ V3 matvec(const M3& m, V3 v) {
    return mk3(fmaf(m.c0.x, v.x, fmaf(m.c1.x, v.y, m.c2.x * v.z)),
               fmaf(m.c0.y, v.x, fmaf(m.c1.y, v.y, m.c2.y * v.z)),
               fmaf(m.c0.z, v.x, fmaf(m.c1.z, v.y, m.c2.z * v.z)));
}
__device__ __forceinline__ M3 matmul(const M3& a, const M3& b) {
    M3 r; r.c0 = matvec(a, b.c0); r.c1 = matvec(a, b.c1); r.c2 = matvec(a, b.c2); return r;
}

// 6D continuous rotation rep -> 3x3 matrix (columns b1,b2,b3).
__device__ __forceinline__ M3 conv6d(V3 a1, V3 a2) {
    float n1 = fmaf(a1.x, a1.x, fmaf(a1.y, a1.y, a1.z * a1.z));
    float i1 = rsqrtf(fmaxf(n1, 1e-24f));
    V3 b1 = mk3(a1.x * i1, a1.y * i1, a1.z * i1);

    float dp = fmaf(b1.x, a2.x, fmaf(b1.y, a2.y, b1.z * a2.z));
    V3 t = mk3(fmaf(-dp, b1.x, a2.x), fmaf(-dp, b1.y, a2.y), fmaf(-dp, b1.z, a2.z));
    float n2 = fmaf(t.x, t.x, fmaf(t.y, t.y, t.z * t.z));
    float i2 = rsqrtf(fmaxf(n2, 1e-24f));
    V3 b2 = mk3(t.x * i2, t.y * i2, t.z * i2);

    V3 b3 = mk3(b1.y * b2.z - b1.z * b2.y,
                b1.z * b2.x - b1.x * b2.z,
                b1.x * b2.y - b1.y * b2.x);
    M3 m; m.c0 = b1; m.c1 = b2; m.c2 = b3; return m;
}

// two alignment forms of a 6-float span inside consecutive float4s
__device__ __forceinline__ M3 convA(float4 p, float4 q) {   // span starts at comp 0
    return conv6d(mk3(p.x, p.y, p.z), mk3(p.w, q.x, q.y));
}
__device__ __forceinline__ M3 convB(float4 p, float4 q) {   // span starts at comp 2
    return conv6d(mk3(p.z, p.w, q.x), mk3(q.y, q.z, q.w));
}

__device__ __forceinline__ float dst(V3 p, V3 g) {
    float dx = p.x - g.x, dy = p.y - g.y, dz = p.z - g.z;
    return sqrtf(fmaf(dx, dx, fmaf(dy, dy, dz * dz)));
}

__device__ __forceinline__ void cpa16(void* smem_dst, const void* gmem_src) {
    uint32_t sa = (uint32_t)__cvta_generic_to_shared(smem_dst);
    asm volatile("cp.async.cg.shared.global [%0], [%1], 16;\n" :: "r"(sa), "l"(gmem_src));
}
__device__ __forceinline__ void cpa_commit_wait() {
    asm volatile("cp.async.commit_group;\n");
    asm volatile("cp.async.wait_group 0;\n");
}

// Champion (R4/R14) structure; staging via cp.async (GMEM->SMEM direct, no reg
// round-trip -> ~96 regs natural), pred rows 8-wide XOR-swizzled -> 44.5KB smem.
// 5 CTAs/SM fit BOTH budgets naturally (no forced cap -> no spills).
__global__ void __launch_bounds__(TPB)
fk_mpjpe_kernel(const float* __restrict__ pred,   // [FRAMES, 20, 3]
                const float* __restrict__ rot,    // [FRAMES, 22, 6]
                const float* __restrict__ off,    // [22, 3]
                float* __restrict__ out)
{
    __shared__ float4 srot [TPB * 13];   // 12 rot words/frame + pad (conflict-free)
    __shared__ float4 spred[TPB * 8];    //  8 pred words/frame, XOR-swizzled rows
    __shared__ float  soff[66];
    __shared__ float  wsum[TPB / 32];
    __shared__ bool   is_last;

    const int tid = threadIdx.x;
    const size_t f0 = (size_t)blockIdx.x * TPB;
    const float4* Rg = (const float4*)rot  + f0 * 33;
    const float4* Pg = (const float4*)pred + f0 * 15;

    if (tid < 66) soff[tid] = off[tid];

    // ================= PHASE 1 staging: rot words 3..14, pred words 0..7 (cp.async)
    #pragma unroll
    for (int j = 0; j < 12; j++) {
        unsigned i = tid + j * TPB;
        unsigned fr = i / 12u, w = i % 12u;
        cpa16(&srot[fr * 13 + w], Rg + fr * 33 + 3 + w);
    }
    #pragma unroll
    for (int j = 0; j < 8; j++) {
        unsigned i = tid + j * TPB;
        unsigned fr = i >> 3, w = i & 7u;
        cpa16(&spred[fr * 8 + (w ^ (fr & 7u))], Pg + fr * 15 + w);
    }
    cpa_commit_wait();
    __syncthreads();

    const unsigned swz = tid & 7u;
    const float4* qb = srot  + tid * 13;   // rot word w (phase1): qb[w-3]
    const float4* pb = spred + tid * 8;    // pred word w (phase1): pb[w ^ swz]

    #define Q1(w)  qb[(w) - 3]
    #define P1(w)  pb[(w) ^ swz]
    #define OFF3(i) mk3(soff[3*(i)], soff[3*(i)+1], soff[3*(i)+2])

    float acc = 0.f;
    M3 G9; V3 pos9;

    // ---- chain: 3 -> 6 -> 9 (trunk; G9/pos9 carried to phase 2) ----
    {
        M3 G3 = convB(Q1(4), Q1(5));
        V3 pos3 = OFF3(3);
        float4 p0 = P1(0), p1 = P1(1);
        acc += dst(mk3(p0.w, p1.x, p1.y), pos3);                  // k=1
        M3 G6 = matmul(G3, convA(Q1(9), Q1(10)));
        V3 pos6 = v_add(pos3, matvec(G3, OFF3(6)));
        float4 p3 = P1(3);
        acc += dst(mk3(p3.x, p3.y, p3.z), pos6);                  // k=4
        G9 = matmul(G6, convB(Q1(13), Q1(14)));
        pos9 = v_add(pos6, matvec(G6, OFF3(9)));
        float4 p5 = P1(5);
        acc += dst(mk3(p5.y, p5.z, p5.w), pos9);                  // k=7
    }

    // ---- chain: 1(identity) -> 4 -> 7 -> 10 ----
    {
        M3 G4 = convA(Q1(6), Q1(7));
        V3 pos4 = v_add(OFF3(1), OFF3(4));
        float4 p1 = P1(1), p2 = P1(2);
        acc += dst(mk3(p1.z, p1.w, p2.x), pos4);                  // k=2
        M3 G7 = matmul(G4, convB(Q1(10), Q1(11)));
        V3 pos7 = v_add(pos4, matvec(G4, OFF3(7)));
        float4 p3 = P1(3), p4 = P1(4);
        acc += dst(mk3(p3.w, p4.x, p4.y), pos7);                  // k=5
        V3 pos10 = v_add(pos7, matvec(G7, OFF3(10)));
        float4 p6 = P1(6);
        acc += dst(mk3(p6.x, p6.y, p6.z), pos10);                 // k=8
    }

    // ---- chain: 2 -> 5 -> 8 -> 11 ----
    {
        M3 G2 = convA(Q1(3), Q1(4));
        V3 pos2 = OFF3(2);
        float4 p0 = P1(0);
        acc += dst(mk3(p0.x, p0.y, p0.z), pos2);                  // k=0
        M3 G5 = matmul(G2, convB(Q1(7), Q1(8)));
        V3 pos5 = v_add(pos2, matvec(G2, OFF3(5)));
        float4 p2 = P1(2);
        acc += dst(mk3(p2.y, p2.z, p2.w), pos5);                  // k=3
        M3 G8 = matmul(G5, convA(Q1(12), Q1(13)));
        V3 pos8 = v_add(pos5, matvec(G5, OFF3(8)));
        float4 p4 = P1(4), p5 = P1(5);
        acc += dst(mk3(p4.z, p4.w, p5.x), pos8);                  // k=6
        V3 pos11 = v_add(pos8, matvec(G8, OFF3(11)));
        float4 p6 = P1(6), p7 = P1(7);
        acc += dst(mk3(p6.w, p7.x, p7.y), pos11);                 // k=9
    }

    // ================= PHASE 2 staging: rot words 18..29, pred words 7..14
    __syncthreads();   // all phase-1 smem reads done
    #pragma unroll
    for (int j = 0; j < 12; j++) {
        unsigned i = tid + j * TPB;
        unsigned fr = i / 12u, w = i % 12u;
        cpa16(&srot[fr * 13 + w], Rg + fr * 33 + 18 + w);
    }
    #pragma unroll
    for (int j = 0; j < 8; j++) {
        unsigned i = tid + j * TPB;
        unsigned fr = i >> 3, w = i & 7u;
        cpa16(&spred[fr * 8 + (w ^ (fr & 7u))], Pg + fr * 15 + 7 + w);
    }
    cpa_commit_wait();
    __syncthreads();

    #define Q2(w)  qb[(w) - 18]
    #define P2(w)  pb[((w) - 7) ^ swz]

    // ---- branch 12 -> 15 ----
    {
        M3 G12 = matmul(G9, convA(Q2(18), Q2(19)));
        V3 pos12 = v_add(pos9, matvec(G9, OFF3(12)));
        float4 p7 = P2(7), p8 = P2(8);
        acc += dst(mk3(p7.z, p7.w, p8.x), pos12);                 // k=10
        V3 pos15 = v_add(pos12, matvec(G12, OFF3(15)));
        float4 p9 = P2(9), p10 = P2(10);
        acc += dst(mk3(p9.w, p10.x, p10.y), pos15);               // k=13
    }

    // ---- branch 13 -> 16 -> 18 -> 20 ----
    {
        M3 G13 = matmul(G9, convB(Q2(19), Q2(20)));
        V3 pos13 = v_add(pos9, matvec(G9, OFF3(13)));
        float4 p8 = P2(8);
        acc += dst(mk3(p8.y, p8.z, p8.w), pos13);                 // k=11
        M3 G16 = matmul(G13, convA(Q2(24), Q2(25)));
        V3 pos16 = v_add(pos13, matvec(G13, OFF3(16)));
        float4 p10 = P2(10), p11 = P2(11);
        acc += dst(mk3(p10.z, p10.w, p11.x), pos16);              // k=14
        M3 G18 = matmul(G16, convA(Q2(27), Q2(28)));
        V3 pos18 = v_add(pos16, matvec(G16, OFF3(18)));
        float4 p12 = P2(12);
        acc += dst(mk3(p12.x, p12.y, p12.z), pos18);              // k=16
        V3 pos20 = v_add(pos18, matvec(G18, OFF3(20)));
        float4 p13 = P2(13), p14 = P2(14);
        acc += dst(mk3(p13.z, p13.w, p14.x), pos20);              // k=18
    }

    // ---- branch 14 -> 17 -> 19 -> 21 ----
    {
        M3 G14 = matmul(G9, convA(Q2(21), Q2(22)));
        V3 pos14 = v_add(pos9, matvec(G9, OFF3(14)));
        float4 p9 = P2(9);
        acc += dst(mk3(p9.x, p9.y, p9.z), pos14);                 // k=12
        M3 G17 = matmul(G14, convB(Q2(25), Q2(26)));
        V3 pos17 = v_add(pos14, matvec(G14, OFF3(17)));
        float4 p11 = P2(11);
        acc += dst(mk3(p11.y, p11.z, p11.w), pos17);              // k=15
        M3 G19 = matmul(G17, convB(Q2(28), Q2(29)));
        V3 pos19 = v_add(pos17, matvec(G17, OFF3(19)));
        float4 p12 = P2(12), p13 = P2(13);
        acc += dst(mk3(p12.w, p13.x, p13.y), pos19);              // k=17
        V3 pos21 = v_add(pos19, matvec(G19, OFF3(21)));
        float4 p14 = P2(14);
        acc += dst(mk3(p14.y, p14.z, p14.w), pos21);              // k=19
    }

    #undef Q1
    #undef P1
    #undef Q2
    #undef P2
    #undef OFF3

    // ---- deterministic block reduction ----
    #pragma unroll
    for (int o = 16; o > 0; o >>= 1)
        acc += __shfl_down_sync(0xffffffffu, acc, o);

    int lane = tid & 31, wid = tid >> 5;
    if (lane == 0) wsum[wid] = acc;
    __syncthreads();

    if (tid == 0) {
        float s = 0.f;
        #pragma unroll
        for (int i = 0; i < TPB / 32; i++) s += wsum[i];
        g_partial[blockIdx.x] = s;
        __threadfence();
        unsigned prev = atomicAdd(&g_count, 1u);
        is_last = (prev == NBLK - 1);
    }
    __syncthreads();

    // ---- last block folds all partials (fixed order -> deterministic) ----
    if (is_last) {
        float s = 0.f;
        #pragma unroll
        for (int j = 0; j < NBLK / TPB; j++) {
            const float* addr = g_partial + tid + j * TPB;
            float v;
            asm volatile("ld.global.cg.f32 %0, [%1];" : "=f"(v) : "l"(addr));
            s += v;
        }
        __shared__ float sh[TPB];
        sh[tid] = s;
        __syncthreads();
        #pragma unroll
        for (int k = TPB / 2; k > 0; k >>= 1) {
            if (tid < k) sh[tid] += sh[tid + k];
            __syncthreads();
        }
        if (tid == 0) {
            out[0] = sh[0] * (1000.0f / (float)(FRAMES * 20));
            g_count = 0;   // reset for next graph replay
        }
    }
}

extern "C" void kernel_launch(void* const* d_in, const int* in_sizes, int n_in,
                              void* d_out, int out_size) {
    const float* pred = (const float*)d_in[0];   // pred_pos [32,4096,20,3]
    const float* rot  = (const float*)d_in[1];   // gt_rot   [32,4096,22,6]
    const float* off  = (const float*)d_in[2];   // offsets  [22,3]
    float* out = (float*)d_out;

    fk_mpjpe_kernel<<<NBLK, TPB>>>(pred, rot, off, out);
}